// round 9
// baseline (speedup 1.0000x reference)
#include <cuda_runtime.h>
#include <cuda_bf16.h>
#include <math.h>

#define FULLMASK 0xFFFFFFFFu

// Problem constants (fixed by the dataset)
#define NMAX   16384
#define INCH   128
#define SDIM   4
#define PDIM   64
#define OUTCH  128
#define KNN    50
#define NPER   4096   // nodes per segment (16384 / 4 splits)
#define CAP2   256    // per-query collection buffer (per-CTA, reused)

// ---------------- device scratch (no allocation allowed) ----------------
__device__ float g_space[NMAX * SDIM];
__device__ float g_prop [NMAX * PDIM];
__device__ int   g_idx  [NMAX * KNN];
__device__ float g_w    [NMAX * KNN];   // exp(-10*d2), precomputed for k3

// Bit-exact replication of reference arithmetic (do not touch):
__device__ __forceinline__ float xla_sq4(float4 c) {
    return __fadd_rn(__fadd_rn(__fadd_rn(__fmul_rn(c.x, c.x), __fmul_rn(c.y, c.y)),
                               __fmul_rn(c.z, c.z)),
                     __fmul_rn(c.w, c.w));
}
__device__ __forceinline__ float cublas_dot4(float4 a, float4 b) {
    return __fmaf_rn(a.w, b.w, __fmaf_rn(a.z, b.z, __fmaf_rn(a.y, b.y, __fmul_rn(a.x, b.x))));
}
__device__ __forceinline__ float d2f(float4 cq, float sqq, float4 cj, float sqj) {
    const float dot = cublas_dot4(cq, cj);
    const float t   = __fadd_rn(sqq, sqj);
    return fmaxf(__fadd_rn(t, __fmul_rn(-2.0f, dot)), 0.0f);
}

// ---------------- K1: space = x@Ws + bs ; prop = x@Wp + bp ----------------
// 64 nodes/block, 256 threads (measured best: 22.4us).
__global__ __launch_bounds__(256) void k1_project(
        const float* __restrict__ x,
        const float* __restrict__ Ws, const float* __restrict__ bs,
        const float* __restrict__ Wp, const float* __restrict__ bp,
        float* __restrict__ out, int N) {
    __shared__ __align__(16) float sx [64 * INCH];        // 32 KB
    __shared__ __align__(16) float sWp[INCH * PDIM];      // 32 KB
    __shared__ float sWs[INCH * SDIM];                    //  2 KB
    const int tid = threadIdx.x;
    const int base = blockIdx.x * 64;

    for (int i = tid * 4; i < 64 * INCH; i += 1024)
        *(float4*)&sx[i] = *(const float4*)&x[(size_t)base * INCH + i];
    for (int i = tid * 4; i < INCH * PDIM; i += 1024)
        *(float4*)&sWp[i] = *(const float4*)&Wp[i];
    for (int i = tid; i < INCH * SDIM; i += 256) sWs[i] = Ws[i];
    __syncthreads();

    // ---- prop: register tile 4 nodes x 4 channels ----
    {
        const int cg = (tid & 15) * 4;          // c0
        const int ng = (tid >> 4) * 4;          // n0
        float acc[4][4];
        #pragma unroll
        for (int i = 0; i < 4; i++) {
            const float4 b4 = *(const float4*)&bp[cg];
            acc[i][0] = b4.x; acc[i][1] = b4.y; acc[i][2] = b4.z; acc[i][3] = b4.w;
        }
        for (int kk = 0; kk < INCH; kk += 4) {
            float4 xv[4];
            #pragma unroll
            for (int i = 0; i < 4; i++) xv[i] = *(const float4*)&sx[(ng + i) * INCH + kk];
            #pragma unroll
            for (int q = 0; q < 4; q++) {
                const float4 w4 = *(const float4*)&sWp[(kk + q) * PDIM + cg];
                #pragma unroll
                for (int i = 0; i < 4; i++) {
                    const float xs = (q == 0) ? xv[i].x : (q == 1) ? xv[i].y
                                   : (q == 2) ? xv[i].z : xv[i].w;
                    acc[i][0] = __fmaf_rn(xs, w4.x, acc[i][0]);
                    acc[i][1] = __fmaf_rn(xs, w4.y, acc[i][1]);
                    acc[i][2] = __fmaf_rn(xs, w4.z, acc[i][2]);
                    acc[i][3] = __fmaf_rn(xs, w4.w, acc[i][3]);
                }
            }
        }
        #pragma unroll
        for (int i = 0; i < 4; i++) {
            float4 r; r.x = acc[i][0]; r.y = acc[i][1]; r.z = acc[i][2]; r.w = acc[i][3];
            *(float4*)&g_prop[(size_t)(base + ng + i) * PDIM + cg] = r;
        }
    }

    // ---- space: exact sliced1x4 chain, one thread per (node, cs) ----
    {
        const int node = tid >> 2, cs = tid & 3;
        const float* xr = &sx[node * INCH];
        float s[4];
        #pragma unroll
        for (int sl = 0; sl < 4; sl++) {
            float acc = 0.0f;
            const int k0 = sl * 32;
            #pragma unroll
            for (int kk = 0; kk < 32; kk++)
                acc = __fmaf_rn(xr[k0 + kk], sWs[(k0 + kk) * SDIM + cs], acc);
            s[sl] = acc;
        }
        const float g = __fadd_rn(__fadd_rn(__fadd_rn(s[0], s[1]), s[2]), s[3]);
        const float v = __fadd_rn(g, bs[cs]);
        const int gn = base + node;
        g_space[(size_t)gn * SDIM + cs] = v;
        out[(size_t)N * 228 + (size_t)gn * SDIM + cs] = v;   // space output region
    }
}

// ---------------- K2 v3: CTA-cooperative exact KNN with u16-quantized pass 2 ----
// 256 threads; block handles 16 consecutive queries SERIALLY, all threads on one
// query. Dynamic smem layout (93,184 B total -> 2 CTAs/SM):
//   sC    float4[4096]   65536 B
//   sSq   float [4096]   16384 B
//   sQ16  u16   [4096]    8192 B   (quantized d2: vbits>>16, monotone)
//   sTop  float [256]     1024 B   (per-thread minima)
//   sBuf  u64   [256]     2048 B   (threshold subset keys / collection buffer)
#define K2_SMEM (NPER*16 + NPER*4 + NPER*2 + 256*4 + CAP2*8)

__device__ __forceinline__ void k2_write(unsigned vbits, int j, int rank, int gq,
                                         int segBase, float* __restrict__ out, int N) {
    const float v = __uint_as_float(vbits);
    const int gi = segBase + j;
    g_idx[(size_t)gq * KNN + rank] = gi;
    g_w  [(size_t)gq * KNN + rank] = expf(-10.0f * v);
    out[(size_t)N * 128 + (size_t)gq * KNN + rank] = (float)gi;  // neighbor_idx region
    out[(size_t)N * 178 + (size_t)gq * KNN + rank] = v;          // distsq region
}

__global__ __launch_bounds__(256) void k2_knn(float* __restrict__ out, int N) {
    extern __shared__ unsigned char dsm[];
    float4*             sC   = (float4*)dsm;                                  // 64 KB
    float*              sSq  = (float*)(dsm + NPER * 16);                     // 16 KB
    unsigned short*     sQ16 = (unsigned short*)(dsm + NPER * 20);            //  8 KB
    float*              sTop = (float*)(dsm + NPER * 22);                     //  1 KB
    unsigned long long* sBuf = (unsigned long long*)(dsm + NPER * 22 + 1024); //  2 KB
    __shared__ float    sT;
    __shared__ unsigned scnt;

    const int tid = threadIdx.x;
    const int qBase = blockIdx.x * 16;
    const int segBase = qBase & ~(NPER - 1);

    for (int j = tid; j < NPER; j += 256) {
        const float4 c = *(const float4*)&g_space[(size_t)(segBase + j) * 4];
        sC[j] = c;
        sSq[j] = xla_sq4(c);
    }
    __syncthreads();

    for (int qi = 0; qi < 16; qi++) {
        const int gq = qBase + qi;
        const int ql = gq - segBase;
        const float4 cq = sC[ql];
        const float  sqq = sSq[ql];

        // ---- Pass 1: d2 for all 4096, quantize to u16, per-thread min ----
        float m = INFINITY;
        #pragma unroll
        for (int it = 0; it < 16; it++) {
            const int j = (it << 8) + tid;
            const float v = d2f(cq, sqq, sC[j], sSq[j]);
            sQ16[j] = (unsigned short)(__float_as_uint(v) >> 16);
            m = fminf(m, v);
        }
        sTop[tid] = m;
        __syncthreads();

        // ---- Threshold: warp 0, rank-49 of per-lane-top-2 of the 256 minima ----
        if (tid < 32) {
            unsigned long long k0 = ~0ull, k1 = ~0ull;
            #pragma unroll
            for (int r = 0; r < 8; r++) {
                const int i = tid * 8 + r;
                const unsigned long long k =
                    ((unsigned long long)__float_as_uint(sTop[i]) << 16) | (unsigned)i;
                if (k < k0) { k1 = k0; k0 = k; }
                else if (k < k1) { k1 = k; }
            }
            sBuf[tid * 2]     = k0;
            sBuf[tid * 2 + 1] = k1;
            __syncwarp();
            int r0 = 0, r1 = 0;
            #pragma unroll 8
            for (int n = 0; n < 64; n++) {
                const unsigned long long u = sBuf[n];
                r0 += (u < k0); r1 += (u < k1);
            }
            const bool h = (r0 == 49) || (r1 == 49);
            const float vh = __uint_as_float((unsigned)(((r0 == 49) ? k0 : k1) >> 16));
            const unsigned mm = __ballot_sync(FULLMASK, h);
            const float T = __shfl_sync(FULLMASK, vh, __ffs(mm) - 1);
            if (tid == 0) { sT = T; scnt = 0; }
        }
        __syncthreads();

        const float T = sT;
        const unsigned T16 = __float_as_uint(T) >> 16;

        // ---- Pass 2: scan u16 array; exact recompute only for hits ----
        #pragma unroll
        for (int it = 0; it < 2; it++) {
            const int j0 = (((it << 8) + tid) << 3);       // 8 u16 per thread per it
            const uint4 qv = *(const uint4*)&sQ16[j0];
            const unsigned wrd[4] = {qv.x, qv.y, qv.z, qv.w};
            #pragma unroll
            for (int wi = 0; wi < 4; wi++) {
                const unsigned lo = wrd[wi] & 0xFFFFu;
                const unsigned hi = wrd[wi] >> 16;
                if (lo <= T16) {
                    const int j = j0 + 2 * wi;
                    const float v = d2f(cq, sqq, sC[j], sSq[j]);
                    if (v <= T) {
                        const unsigned p = atomicAdd(&scnt, 1u);
                        if (p < CAP2)
                            sBuf[p] = ((unsigned long long)__float_as_uint(v) << 16) | (unsigned)j;
                    }
                }
                if (hi <= T16) {
                    const int j = j0 + 2 * wi + 1;
                    const float v = d2f(cq, sqq, sC[j], sSq[j]);
                    if (v <= T) {
                        const unsigned p = atomicAdd(&scnt, 1u);
                        if (p < CAP2)
                            sBuf[p] = ((unsigned long long)__float_as_uint(v) << 16) | (unsigned)j;
                    }
                }
            }
        }
        __syncthreads();

        // ---- Finalize: exact rank-sort of collected keys ----
        const unsigned cnt = scnt;
        if (cnt >= KNN && cnt <= CAP2) {
            if (tid < (int)cnt) {
                const unsigned long long key = sBuf[tid];
                int rank = 0;
                for (int n = 0; n < (int)cnt; n++) rank += (sBuf[n] < key);
                if (rank < KNN)
                    k2_write((unsigned)(key >> 16), (int)(key & 0xFFFFull),
                             rank, gq, segBase, out, N);
            }
        } else if (tid < 32) {
            // Exact deterministic fallback (practically never taken).
            const int lane = tid;
            long long prev = -1;
            for (int r = 0; r < KNN; r++) {
                unsigned long long best = ~0ull;
                for (int j = lane; j < NPER; j += 32) {
                    const float v = d2f(cq, sqq, sC[j], sSq[j]);
                    const unsigned long long key =
                        ((unsigned long long)__float_as_uint(v) << 16) | (unsigned)j;
                    if ((long long)key > prev && key < best) best = key;
                }
                #pragma unroll
                for (int off = 16; off; off >>= 1) {
                    const unsigned long long o = __shfl_xor_sync(FULLMASK, best, off);
                    if (o < best) best = o;
                }
                if (lane == 0)
                    k2_write((unsigned)(best >> 16), (int)(best & 0xFFFFull),
                             r, gq, segBase, out, N);
                prev = (long long)best;
            }
        }
        __syncthreads();   // sBuf/sQ16/sTop reused by next query
    }
}

// ---------------- K3: gather + mean/max + output GEMM + relu ----------------
// 32 nodes/block, 256 threads; gather runs 4 nodes concurrently.
__global__ __launch_bounds__(256) void k3_aggregate(
        const float* __restrict__ x,
        const float* __restrict__ Wo, const float* __restrict__ bo,
        float* __restrict__ out) {
    __shared__ __align__(16) float feat[32][2 * PDIM + INCH];   // 32 KB
    __shared__ float swarr[32 * KNN];                            // 6.4 KB
    __shared__ int   sgidx[32 * KNN];                            // 6.4 KB

    const int tid = threadIdx.x;
    const int base = blockIdx.x * 32;

    for (int i = tid * 4; i < 32 * INCH; i += 1024) {
        const int node = i >> 7, c = i & 127;
        *(float4*)&feat[node][c] = *(const float4*)&x[(size_t)(base + node) * INCH + c];
    }
    for (int i = tid; i < 32 * KNN; i += 256) {
        swarr[i] = g_w  [(size_t)base * KNN + i];
        sgidx[i] = g_idx[(size_t)base * KNN + i];
    }
    __syncthreads();

    {
        const int ns = tid >> 6, c = tid & 63;
        for (int nn = ns; nn < 32; nn += 4) {
            const float* wr = &swarr[nn * KNN];
            const int*   ir = &sgidx[nn * KNN];
            float acc = 0.0f, mx = -INFINITY;
            #pragma unroll 5
            for (int r = 0; r < KNN; r++) {
                const float v = g_prop[(size_t)ir[r] * PDIM + c] * wr[r];
                acc += v; mx = fmaxf(mx, v);
            }
            feat[nn][INCH + c]        = acc * (1.0f / (float)KNN);
            feat[nn][INCH + PDIM + c] = mx;
        }
    }
    __syncthreads();

    const int c = tid & 127;
    const int t0 = (tid >> 7) * 16;
    float acc[16];
    #pragma unroll
    for (int t = 0; t < 16; t++) acc[t] = bo[c];
    for (int kk = 0; kk < 2 * PDIM + INCH; kk += 4) {
        const float w0 = Wo[(size_t)(kk + 0) * OUTCH + c];
        const float w1 = Wo[(size_t)(kk + 1) * OUTCH + c];
        const float w2 = Wo[(size_t)(kk + 2) * OUTCH + c];
        const float w3 = Wo[(size_t)(kk + 3) * OUTCH + c];
        #pragma unroll
        for (int t = 0; t < 16; t++) {
            const float4 f = *(const float4*)&feat[t0 + t][kk];
            acc[t] = __fmaf_rn(f.x, w0, acc[t]);
            acc[t] = __fmaf_rn(f.y, w1, acc[t]);
            acc[t] = __fmaf_rn(f.z, w2, acc[t]);
            acc[t] = __fmaf_rn(f.w, w3, acc[t]);
        }
    }
    #pragma unroll
    for (int t = 0; t < 16; t++)
        out[(size_t)(base + t0 + t) * OUTCH + c] = fmaxf(acc[t], 0.0f);
}

// ---------------- launch ----------------
extern "C" void kernel_launch(void* const* d_in, const int* in_sizes, int n_in,
                              void* d_out, int out_size) {
    const float* x  = (const float*)d_in[0];
    const float* Ws = (const float*)d_in[2];
    const float* bs = (const float*)d_in[3];
    const float* Wp = (const float*)d_in[4];
    const float* bp = (const float*)d_in[5];
    const float* Wo = (const float*)d_in[6];
    const float* bo = (const float*)d_in[7];

    const int N = in_sizes[0] / INCH;   // 16384
    float* out = (float*)d_out;

    k1_project<<<N / 64, 256>>>(x, Ws, bs, Wp, bp, out, N);

    cudaFuncSetAttribute(k2_knn, cudaFuncAttributeMaxDynamicSharedMemorySize, K2_SMEM);
    k2_knn<<<N / 16, 256, K2_SMEM>>>(out, N);

    k3_aggregate<<<N / 32, 256>>>(x, Wo, bo, out);

    (void)n_in; (void)in_sizes; (void)out_size;
}

// round 10
// speedup vs baseline: 1.5094x; 1.5094x over previous
#include <cuda_runtime.h>
#include <cuda_bf16.h>
#include <cuda_fp16.h>
#include <math.h>

#define FULLMASK 0xFFFFFFFFu

// Problem constants (fixed by the dataset)
#define NMAX   16384
#define INCH   128
#define SDIM   4
#define PDIM   64
#define OUTCH  128
#define KNN    50
#define NPER   4096   // nodes per segment (16384 / 4 splits)
#define NPAIR  (NPER/2)
#define CAP    192    // collection buffer per query

// ---------------- device scratch (no allocation allowed) ----------------
__device__ float g_space[NMAX * SDIM];
__device__ float g_prop [NMAX * PDIM];
__device__ int   g_idx  [NMAX * KNN];
__device__ float g_w    [NMAX * KNN];   // exp(-10*d2), precomputed for k3

// Bit-exact replication of reference arithmetic (do not touch):
__device__ __forceinline__ float xla_sq4(float4 c) {
    return __fadd_rn(__fadd_rn(__fadd_rn(__fmul_rn(c.x, c.x), __fmul_rn(c.y, c.y)),
                               __fmul_rn(c.z, c.z)),
                     __fmul_rn(c.w, c.w));
}
__device__ __forceinline__ float cublas_dot4(float4 a, float4 b) {
    return __fmaf_rn(a.w, b.w, __fmaf_rn(a.z, b.z, __fmaf_rn(a.y, b.y, __fmul_rn(a.x, b.x))));
}
__device__ __forceinline__ float d2f(float4 cq, float sqq, float4 cj, float sqj) {
    const float dot = cublas_dot4(cq, cj);
    const float t   = __fadd_rn(sqq, sqj);
    return fmaxf(__fadd_rn(t, __fmul_rn(-2.0f, dot)), 0.0f);
}

// ---------------- K1: space = x@Ws + bs ; prop = x@Wp + bp ----------------
// 64 nodes/block, 256 threads (measured best: 22.4us).
__global__ __launch_bounds__(256) void k1_project(
        const float* __restrict__ x,
        const float* __restrict__ Ws, const float* __restrict__ bs,
        const float* __restrict__ Wp, const float* __restrict__ bp,
        float* __restrict__ out, int N) {
    __shared__ __align__(16) float sx [64 * INCH];        // 32 KB
    __shared__ __align__(16) float sWp[INCH * PDIM];      // 32 KB
    __shared__ float sWs[INCH * SDIM];                    //  2 KB
    const int tid = threadIdx.x;
    const int base = blockIdx.x * 64;

    for (int i = tid * 4; i < 64 * INCH; i += 1024)
        *(float4*)&sx[i] = *(const float4*)&x[(size_t)base * INCH + i];
    for (int i = tid * 4; i < INCH * PDIM; i += 1024)
        *(float4*)&sWp[i] = *(const float4*)&Wp[i];
    for (int i = tid; i < INCH * SDIM; i += 256) sWs[i] = Ws[i];
    __syncthreads();

    {
        const int cg = (tid & 15) * 4;
        const int ng = (tid >> 4) * 4;
        float acc[4][4];
        #pragma unroll
        for (int i = 0; i < 4; i++) {
            const float4 b4 = *(const float4*)&bp[cg];
            acc[i][0] = b4.x; acc[i][1] = b4.y; acc[i][2] = b4.z; acc[i][3] = b4.w;
        }
        for (int kk = 0; kk < INCH; kk += 4) {
            float4 xv[4];
            #pragma unroll
            for (int i = 0; i < 4; i++) xv[i] = *(const float4*)&sx[(ng + i) * INCH + kk];
            #pragma unroll
            for (int q = 0; q < 4; q++) {
                const float4 w4 = *(const float4*)&sWp[(kk + q) * PDIM + cg];
                #pragma unroll
                for (int i = 0; i < 4; i++) {
                    const float xs = (q == 0) ? xv[i].x : (q == 1) ? xv[i].y
                                   : (q == 2) ? xv[i].z : xv[i].w;
                    acc[i][0] = __fmaf_rn(xs, w4.x, acc[i][0]);
                    acc[i][1] = __fmaf_rn(xs, w4.y, acc[i][1]);
                    acc[i][2] = __fmaf_rn(xs, w4.z, acc[i][2]);
                    acc[i][3] = __fmaf_rn(xs, w4.w, acc[i][3]);
                }
            }
        }
        #pragma unroll
        for (int i = 0; i < 4; i++) {
            float4 r; r.x = acc[i][0]; r.y = acc[i][1]; r.z = acc[i][2]; r.w = acc[i][3];
            *(float4*)&g_prop[(size_t)(base + ng + i) * PDIM + cg] = r;
        }
    }

    {
        const int node = tid >> 2, cs = tid & 3;
        const float* xr = &sx[node * INCH];
        float s[4];
        #pragma unroll
        for (int sl = 0; sl < 4; sl++) {
            float acc = 0.0f;
            const int k0 = sl * 32;
            #pragma unroll
            for (int kk = 0; kk < 32; kk++)
                acc = __fmaf_rn(xr[k0 + kk], sWs[(k0 + kk) * SDIM + cs], acc);
            s[sl] = acc;
        }
        const float g = __fadd_rn(__fadd_rn(__fadd_rn(s[0], s[1]), s[2]), s[3]);
        const float v = __fadd_rn(g, bs[cs]);
        const int gn = base + node;
        g_space[(size_t)gn * SDIM + cs] = v;
        out[(size_t)N * 228 + (size_t)gn * SDIM + cs] = v;
    }
}

// ---------------- K2 v4: R8 skeleton + half2 SIMD filter sweeps ----------------
// 256 threads = 8 warps; warp owns 2 queries; 16 queries/block; grid 1024.
// smem: sH uint4[2048] 32KB | sSq float[4096] 16KB | sBuf u64[16][CAP] 24KB = 72KB
#define K2_SMEM (NPAIR*16 + NPER*4 + 16*CAP*8)

__device__ __forceinline__ void k2_write(unsigned vbits, int j, int rank, int gq,
                                         int segBase, float* __restrict__ out, int N) {
    const float v = __uint_as_float(vbits);
    const int gi = segBase + j;
    g_idx[(size_t)gq * KNN + rank] = gi;
    g_w  [(size_t)gq * KNN + rank] = expf(-10.0f * v);
    out[(size_t)N * 128 + (size_t)gq * KNN + rank] = (float)gi;
    out[(size_t)N * 178 + (size_t)gq * KNN + rank] = v;
}

// rank-49 of the 96 subset keys (u16 half-bit values, unique idx tiebreak)
__device__ __forceinline__ unsigned select49_u16(const unsigned long long* __restrict__ buf,
                                                 unsigned m0, unsigned m1, unsigned m2,
                                                 int lane) {
    const unsigned long long k0 = ((unsigned long long)m0 << 16) | (unsigned)(lane * 3 + 0);
    const unsigned long long k1 = ((unsigned long long)m1 << 16) | (unsigned)(lane * 3 + 1);
    const unsigned long long k2 = ((unsigned long long)m2 << 16) | (unsigned)(lane * 3 + 2);
    int r0 = 0, r1 = 0, r2 = 0;
    for (int n = 0; n < 96; n++) {
        const unsigned long long u = buf[n];
        r0 += (u < k0); r1 += (u < k1); r2 += (u < k2);
    }
    const bool h = (r0 == 49) || (r1 == 49) || (r2 == 49);
    const unsigned vh = (r0 == 49) ? m0 : ((r1 == 49) ? m1 : m2);
    const unsigned m = __ballot_sync(FULLMASK, h);
    return __shfl_sync(FULLMASK, vh, __ffs(m) - 1);
}

__device__ void k2_finalize(const unsigned long long* __restrict__ buf, unsigned cnt, int gq,
                            float4 cq, float sqq, int segBase, int lane,
                            const float4* __restrict__ gs4, const float* __restrict__ sSq,
                            float* __restrict__ out, int N) {
    if (cnt >= KNN && cnt <= CAP) {
        for (int m = lane; m < (int)cnt; m += 32) {
            const unsigned long long key = buf[m];
            int rank = 0;
            for (int n = 0; n < (int)cnt; n++) rank += (buf[n] < key);
            if (rank < KNN)
                k2_write((unsigned)(key >> 16), (int)(key & 0xFFFFull), rank, gq, segBase, out, N);
        }
    } else {
        // Exact deterministic fallback.
        long long prev = -1;
        for (int r = 0; r < KNN; r++) {
            unsigned long long best = ~0ull;
            for (int j = lane; j < NPER; j += 32) {
                const float v = d2f(cq, sqq, gs4[segBase + j], sSq[j]);
                const unsigned long long key =
                    ((unsigned long long)__float_as_uint(v) << 16) | (unsigned)j;
                if ((long long)key > prev && key < best) best = key;
            }
            #pragma unroll
            for (int off = 16; off; off >>= 1) {
                const unsigned long long o = __shfl_xor_sync(FULLMASK, best, off);
                if (o < best) best = o;
            }
            if (lane == 0)
                k2_write((unsigned)(best >> 16), (int)(best & 0xFFFFull), r, gq, segBase, out, N);
            prev = (long long)best;
        }
    }
}

#define HTOP3(a0, a1, a2, g) do { \
    a2 = __hmin2(a2, __hmax2(a1, g)); a1 = __hmin2(a1, __hmax2(a0, g)); a0 = __hmin2(a0, g); \
} while (0)

__global__ __launch_bounds__(256, 3) void k2_knn(float* __restrict__ out, int N) {
    extern __shared__ unsigned char dsm[];
    uint4*              sH   = (uint4*)dsm;                            // 32 KB
    float*              sSq  = (float*)(dsm + NPAIR * 16);             // 16 KB
    unsigned long long* sBuf = (unsigned long long*)(dsm + NPAIR * 16 + NPER * 4); // 24 KB
    __shared__ unsigned scnt[16];

    const int tid = threadIdx.x;
    const int w = tid >> 5, lane = tid & 31;
    const int qBase = blockIdx.x * 16;
    const int segBase = qBase & ~(NPER - 1);
    const float4* gs4 = (const float4*)g_space;

    // ---- setup: half-packed candidate pairs + exact sq_j ----
    for (int p = tid; p < NPAIR; p += 256) {
        const float4 c0 = gs4[segBase + 2 * p];
        const float4 c1 = gs4[segBase + 2 * p + 1];
        __half2 hx = __floats2half2_rn(c0.x, c1.x);
        __half2 hy = __floats2half2_rn(c0.y, c1.y);
        __half2 hz = __floats2half2_rn(c0.z, c1.z);
        __half2 hw = __floats2half2_rn(c0.w, c1.w);
        uint4 pk;
        pk.x = *reinterpret_cast<unsigned*>(&hx);
        pk.y = *reinterpret_cast<unsigned*>(&hy);
        pk.z = *reinterpret_cast<unsigned*>(&hz);
        pk.w = *reinterpret_cast<unsigned*>(&hw);
        sH[p] = pk;
        sSq[2 * p]     = xla_sq4(c0);
        sSq[2 * p + 1] = xla_sq4(c1);
    }
    if (tid < 16) scnt[tid] = 0;
    __syncthreads();

    const int q0 = qBase + 2 * w, q1 = q0 + 1;
    const float4 cq0 = gs4[q0]; const float sqi0 = xla_sq4(cq0);
    const float4 cq1 = gs4[q1]; const float sqi1 = xla_sq4(cq1);
    // half2 broadcasts of query coords
    const __half2 q0x = __float2half2_rn(cq0.x), q0y = __float2half2_rn(cq0.y),
                  q0z = __float2half2_rn(cq0.z), q0w = __float2half2_rn(cq0.w);
    const __half2 q1x = __float2half2_rn(cq1.x), q1y = __float2half2_rn(cq1.y),
                  q1z = __float2half2_rn(cq1.z), q1w = __float2half2_rn(cq1.w);
    unsigned long long* buf0 = sBuf + (size_t)(2 * w) * CAP;
    unsigned long long* buf1 = buf0 + CAP;

    // ---- Pass 1: half2 centered distances, per-SIMD-lane top-3 ----
    const __half2 hinf = __float2half2_rn(6.0e4f);
    __half2 a0 = hinf, a1 = hinf, a2 = hinf;   // query 0
    __half2 b0 = hinf, b1 = hinf, b2 = hinf;   // query 1
    for (int p = lane; p < NPAIR; p += 32) {
        const uint4 pk = sH[p];
        const __half2 cx = *reinterpret_cast<const __half2*>(&pk.x);
        const __half2 cy = *reinterpret_cast<const __half2*>(&pk.y);
        const __half2 cz = *reinterpret_cast<const __half2*>(&pk.z);
        const __half2 cw = *reinterpret_cast<const __half2*>(&pk.w);
        {
            const __half2 dx = __hsub2(q0x, cx), dy = __hsub2(q0y, cy),
                          dz = __hsub2(q0z, cz), dw = __hsub2(q0w, cw);
            __half2 g = __hmul2(dx, dx);
            g = __hfma2(dy, dy, g); g = __hfma2(dz, dz, g); g = __hfma2(dw, dw, g);
            HTOP3(a0, a1, a2, g);
        }
        {
            const __half2 dx = __hsub2(q1x, cx), dy = __hsub2(q1y, cy),
                          dz = __hsub2(q1z, cz), dw = __hsub2(q1w, cw);
            __half2 g = __hmul2(dx, dx);
            g = __hfma2(dy, dy, g); g = __hfma2(dz, dz, g); g = __hfma2(dw, dw, g);
            HTOP3(b0, b1, b2, g);
        }
    }

    // ---- merge SIMD halves -> scalar top-3 (u16 half bits, monotone for g>=0) ----
    unsigned T16_0, T16_1;
    {
        const unsigned ua0 = *reinterpret_cast<const unsigned*>(&a0);
        const unsigned ua1 = *reinterpret_cast<const unsigned*>(&a1);
        const unsigned ua2 = *reinterpret_cast<const unsigned*>(&a2);
        const unsigned l0 = ua0 & 0xFFFFu, h0 = ua0 >> 16;
        const unsigned l1 = ua1 & 0xFFFFu, h1 = ua1 >> 16;
        const unsigned l2 = ua2 & 0xFFFFu, h2 = ua2 >> 16;
        const unsigned m0 = min(l0, h0);
        const unsigned u0 = max(l0, h0), t1 = min(l1, h1), c2 = min(l2, h2);
        const unsigned m1 = min(u0, t1);
        const unsigned m2 = max(min(u0, t1), min(max(u0, t1), c2));
        buf0[lane * 3 + 0] = ((unsigned long long)m0 << 16) | (unsigned)(lane * 3 + 0);
        buf0[lane * 3 + 1] = ((unsigned long long)m1 << 16) | (unsigned)(lane * 3 + 1);
        buf0[lane * 3 + 2] = ((unsigned long long)m2 << 16) | (unsigned)(lane * 3 + 2);
        __syncwarp();
        const unsigned sel = select49_u16(buf0, m0, m1, m2, lane);
        const float Tf = __half2float(__ushort_as_half((unsigned short)sel));
        const float Tm = Tf + 3.0e-3f + 0.01f * Tf;
        T16_0 = (unsigned)__half_as_ushort(__float2half_ru(Tm));
        __syncwarp();
    }
    {
        const unsigned ub0 = *reinterpret_cast<const unsigned*>(&b0);
        const unsigned ub1 = *reinterpret_cast<const unsigned*>(&b1);
        const unsigned ub2 = *reinterpret_cast<const unsigned*>(&b2);
        const unsigned l0 = ub0 & 0xFFFFu, h0 = ub0 >> 16;
        const unsigned l1 = ub1 & 0xFFFFu, h1 = ub1 >> 16;
        const unsigned l2 = ub2 & 0xFFFFu, h2 = ub2 >> 16;
        const unsigned m0 = min(l0, h0);
        const unsigned u0 = max(l0, h0), t1 = min(l1, h1), c2 = min(l2, h2);
        const unsigned m1 = min(u0, t1);
        const unsigned m2 = max(min(u0, t1), min(max(u0, t1), c2));
        buf1[lane * 3 + 0] = ((unsigned long long)m0 << 16) | (unsigned)(lane * 3 + 0);
        buf1[lane * 3 + 1] = ((unsigned long long)m1 << 16) | (unsigned)(lane * 3 + 1);
        buf1[lane * 3 + 2] = ((unsigned long long)m2 << 16) | (unsigned)(lane * 3 + 2);
        __syncwarp();
        const unsigned sel = select49_u16(buf1, m0, m1, m2, lane);
        const float Tf = __half2float(__ushort_as_half((unsigned short)sel));
        const float Tm = Tf + 3.0e-3f + 0.01f * Tf;
        T16_1 = (unsigned)__half_as_ushort(__float2half_ru(Tm));
        __syncwarp();
    }

    // ---- Pass 2: rescan half distances; exact recompute for hits ----
    unsigned* cnt0 = &scnt[2 * w];
    unsigned* cnt1 = &scnt[2 * w + 1];
    for (int p = lane; p < NPAIR; p += 32) {
        const uint4 pk = sH[p];
        const __half2 cx = *reinterpret_cast<const __half2*>(&pk.x);
        const __half2 cy = *reinterpret_cast<const __half2*>(&pk.y);
        const __half2 cz = *reinterpret_cast<const __half2*>(&pk.z);
        const __half2 cw = *reinterpret_cast<const __half2*>(&pk.w);
        // query 0
        {
            const __half2 dx = __hsub2(q0x, cx), dy = __hsub2(q0y, cy),
                          dz = __hsub2(q0z, cz), dw = __hsub2(q0w, cw);
            __half2 g = __hmul2(dx, dx);
            g = __hfma2(dy, dy, g); g = __hfma2(dz, dz, g); g = __hfma2(dw, dw, g);
            const unsigned ug = *reinterpret_cast<const unsigned*>(&g);
            if ((ug & 0xFFFFu) <= T16_0) {
                const int j = 2 * p;
                const float v = d2f(cq0, sqi0, gs4[segBase + j], sSq[j]);
                const unsigned pos = atomicAdd(cnt0, 1u);
                if (pos < CAP)
                    buf0[pos] = ((unsigned long long)__float_as_uint(v) << 16) | (unsigned)j;
            }
            if ((ug >> 16) <= T16_0) {
                const int j = 2 * p + 1;
                const float v = d2f(cq0, sqi0, gs4[segBase + j], sSq[j]);
                const unsigned pos = atomicAdd(cnt0, 1u);
                if (pos < CAP)
                    buf0[pos] = ((unsigned long long)__float_as_uint(v) << 16) | (unsigned)j;
            }
        }
        // query 1
        {
            const __half2 dx = __hsub2(q1x, cx), dy = __hsub2(q1y, cy),
                          dz = __hsub2(q1z, cz), dw = __hsub2(q1w, cw);
            __half2 g = __hmul2(dx, dx);
            g = __hfma2(dy, dy, g); g = __hfma2(dz, dz, g); g = __hfma2(dw, dw, g);
            const unsigned ug = *reinterpret_cast<const unsigned*>(&g);
            if ((ug & 0xFFFFu) <= T16_1) {
                const int j = 2 * p;
                const float v = d2f(cq1, sqi1, gs4[segBase + j], sSq[j]);
                const unsigned pos = atomicAdd(cnt1, 1u);
                if (pos < CAP)
                    buf1[pos] = ((unsigned long long)__float_as_uint(v) << 16) | (unsigned)j;
            }
            if ((ug >> 16) <= T16_1) {
                const int j = 2 * p + 1;
                const float v = d2f(cq1, sqi1, gs4[segBase + j], sSq[j]);
                const unsigned pos = atomicAdd(cnt1, 1u);
                if (pos < CAP)
                    buf1[pos] = ((unsigned long long)__float_as_uint(v) << 16) | (unsigned)j;
            }
        }
    }
    __syncwarp();

    // ---- Final exact rank-sort + writes ----
    k2_finalize(buf0, *cnt0, q0, cq0, sqi0, segBase, lane, gs4, sSq, out, N);
    k2_finalize(buf1, *cnt1, q1, cq1, sqi1, segBase, lane, gs4, sSq, out, N);
}

// ---------------- K3: gather + mean/max + output GEMM + relu ----------------
__global__ __launch_bounds__(256) void k3_aggregate(
        const float* __restrict__ x,
        const float* __restrict__ Wo, const float* __restrict__ bo,
        float* __restrict__ out) {
    __shared__ __align__(16) float feat[32][2 * PDIM + INCH];   // 32 KB
    __shared__ float swarr[32 * KNN];
    __shared__ int   sgidx[32 * KNN];

    const int tid = threadIdx.x;
    const int base = blockIdx.x * 32;

    for (int i = tid * 4; i < 32 * INCH; i += 1024) {
        const int node = i >> 7, c = i & 127;
        *(float4*)&feat[node][c] = *(const float4*)&x[(size_t)(base + node) * INCH + c];
    }
    for (int i = tid; i < 32 * KNN; i += 256) {
        swarr[i] = g_w  [(size_t)base * KNN + i];
        sgidx[i] = g_idx[(size_t)base * KNN + i];
    }
    __syncthreads();

    {
        const int ns = tid >> 6, c = tid & 63;
        for (int nn = ns; nn < 32; nn += 4) {
            const float* wr = &swarr[nn * KNN];
            const int*   ir = &sgidx[nn * KNN];
            float acc = 0.0f, mx = -INFINITY;
            #pragma unroll 5
            for (int r = 0; r < KNN; r++) {
                const float v = g_prop[(size_t)ir[r] * PDIM + c] * wr[r];
                acc += v; mx = fmaxf(mx, v);
            }
            feat[nn][INCH + c]        = acc * (1.0f / (float)KNN);
            feat[nn][INCH + PDIM + c] = mx;
        }
    }
    __syncthreads();

    const int c = tid & 127;
    const int t0 = (tid >> 7) * 16;
    float acc[16];
    #pragma unroll
    for (int t = 0; t < 16; t++) acc[t] = bo[c];
    for (int kk = 0; kk < 2 * PDIM + INCH; kk += 4) {
        const float w0 = Wo[(size_t)(kk + 0) * OUTCH + c];
        const float w1 = Wo[(size_t)(kk + 1) * OUTCH + c];
        const float w2 = Wo[(size_t)(kk + 2) * OUTCH + c];
        const float w3 = Wo[(size_t)(kk + 3) * OUTCH + c];
        #pragma unroll
        for (int t = 0; t < 16; t++) {
            const float4 f = *(const float4*)&feat[t0 + t][kk];
            acc[t] = __fmaf_rn(f.x, w0, acc[t]);
            acc[t] = __fmaf_rn(f.y, w1, acc[t]);
            acc[t] = __fmaf_rn(f.z, w2, acc[t]);
            acc[t] = __fmaf_rn(f.w, w3, acc[t]);
        }
    }
    #pragma unroll
    for (int t = 0; t < 16; t++)
        out[(size_t)(base + t0 + t) * OUTCH + c] = fmaxf(acc[t], 0.0f);
}

// ---------------- launch ----------------
extern "C" void kernel_launch(void* const* d_in, const int* in_sizes, int n_in,
                              void* d_out, int out_size) {
    const float* x  = (const float*)d_in[0];
    const float* Ws = (const float*)d_in[2];
    const float* bs = (const float*)d_in[3];
    const float* Wp = (const float*)d_in[4];
    const float* bp = (const float*)d_in[5];
    const float* Wo = (const float*)d_in[6];
    const float* bo = (const float*)d_in[7];

    const int N = in_sizes[0] / INCH;   // 16384
    float* out = (float*)d_out;

    k1_project<<<N / 64, 256>>>(x, Ws, bs, Wp, bp, out, N);

    cudaFuncSetAttribute(k2_knn, cudaFuncAttributeMaxDynamicSharedMemorySize, K2_SMEM);
    k2_knn<<<N / 16, 256, K2_SMEM>>>(out, N);

    k3_aggregate<<<N / 32, 256>>>(x, Wo, bo, out);

    (void)n_in; (void)in_sizes; (void)out_size;
}

// round 11
// speedup vs baseline: 1.5856x; 1.0505x over previous
#include <cuda_runtime.h>
#include <cuda_bf16.h>
#include <math.h>

#define FULLMASK 0xFFFFFFFFu

// Problem constants (fixed by the dataset)
#define NMAX   16384
#define INCH   128
#define SDIM   4
#define PDIM   64
#define OUTCH  128
#define KNN    50
#define NPER   4096   // nodes per segment (16384 / 4 splits)
#define NPAIR  (NPER/2)
#define CAP    128    // collection buffer per query

typedef unsigned long long u64t;

// ---------------- device scratch (no allocation allowed) ----------------
__device__ float g_space[NMAX * SDIM];
__device__ float g_prop [NMAX * PDIM];
__device__ int   g_idx  [NMAX * KNN];
__device__ float g_w    [NMAX * KNN];   // exp(-10*d2), precomputed for k3

// Bit-exact replication of reference arithmetic (do not touch):
__device__ __forceinline__ float xla_sq4(float4 c) {
    return __fadd_rn(__fadd_rn(__fadd_rn(__fmul_rn(c.x, c.x), __fmul_rn(c.y, c.y)),
                               __fmul_rn(c.z, c.z)),
                     __fmul_rn(c.w, c.w));
}
__device__ __forceinline__ float cublas_dot4(float4 a, float4 b) {
    return __fmaf_rn(a.w, b.w, __fmaf_rn(a.z, b.z, __fmaf_rn(a.y, b.y, __fmul_rn(a.x, b.x))));
}
__device__ __forceinline__ float d2f(float4 cq, float sqq, float4 cj, float sqj) {
    const float dot = cublas_dot4(cq, cj);
    const float t   = __fadd_rn(sqq, sqj);
    return fmaxf(__fadd_rn(t, __fmul_rn(-2.0f, dot)), 0.0f);
}

// ---------------- packed fp32x2 helpers (sm_103a) ----------------
__device__ __forceinline__ u64t p2_pack(float lo, float hi) {
    u64t r; asm("mov.b64 %0, {%1, %2};" : "=l"(r) : "f"(lo), "f"(hi)); return r;
}
__device__ __forceinline__ void p2_unpack(u64t v, float& lo, float& hi) {
    asm("mov.b64 {%0, %1}, %2;" : "=f"(lo), "=f"(hi) : "l"(v));
}
__device__ __forceinline__ u64t p2_mul(u64t a, u64t b) {
    u64t r; asm("mul.rn.f32x2 %0, %1, %2;" : "=l"(r) : "l"(a), "l"(b)); return r;
}
__device__ __forceinline__ u64t p2_add(u64t a, u64t b) {
    u64t r; asm("add.rn.f32x2 %0, %1, %2;" : "=l"(r) : "l"(a), "l"(b)); return r;
}
__device__ __forceinline__ u64t p2_fma(u64t a, u64t b, u64t c) {
    u64t r; asm("fma.rn.f32x2 %0, %1, %2, %3;" : "=l"(r) : "l"(a), "l"(b), "l"(c)); return r;
}
__device__ __forceinline__ u64t mk64(unsigned lo, unsigned hi) {
    u64t r; asm("mov.b64 %0, {%1, %2};" : "=l"(r) : "r"(lo), "r"(hi)); return r;
}

// per-lane two candidates, one query: same RN op sequence as d2f (per lane)
__device__ __forceinline__ u64t d2pair(u64t qx2, u64t qy2, u64t qz2, u64t qw2,
                                       u64t sqq2, uint4 A, uint4 B, u64t sj2, u64t neg2) {
    const u64t x2 = mk64(A.x, A.y), y2 = mk64(A.z, A.w);
    const u64t z2 = mk64(B.x, B.y), w2 = mk64(B.z, B.w);
    u64t dot = p2_mul(qx2, x2);
    dot = p2_fma(qy2, y2, dot);
    dot = p2_fma(qz2, z2, dot);
    dot = p2_fma(qw2, w2, dot);
    return p2_add(p2_add(sqq2, sj2), p2_mul(neg2, dot));
}

#define TOP2_UPD(a0, a1, v) do { a1 = fminf(a1, fmaxf(a0, v)); a0 = fminf(a0, v); } while (0)

// ---------------- K1a: space = x@Ws + bs (exact sliced1x4 chain) ----------------
__global__ __launch_bounds__(256) void k1a_space(
        const float* __restrict__ x,
        const float* __restrict__ Ws, const float* __restrict__ bs,
        float* __restrict__ out, int N) {
    __shared__ __align__(16) float sx[64 * INCH];   // 32 KB
    __shared__ float sWs[INCH * SDIM];              //  2 KB
    const int tid = threadIdx.x;
    const int base = blockIdx.x * 64;

    for (int i = tid * 4; i < 64 * INCH; i += 1024)
        *(float4*)&sx[i] = *(const float4*)&x[(size_t)base * INCH + i];
    for (int i = tid; i < INCH * SDIM; i += 256) sWs[i] = Ws[i];
    __syncthreads();

    const int node = tid >> 2, cs = tid & 3;
    const float* xr = &sx[node * INCH];
    float s[4];
    #pragma unroll
    for (int sl = 0; sl < 4; sl++) {
        float acc = 0.0f;
        const int k0 = sl * 32;
        #pragma unroll
        for (int kk = 0; kk < 32; kk++)
            acc = __fmaf_rn(xr[k0 + kk], sWs[(k0 + kk) * SDIM + cs], acc);
        s[sl] = acc;
    }
    const float g = __fadd_rn(__fadd_rn(__fadd_rn(s[0], s[1]), s[2]), s[3]);
    const float v = __fadd_rn(g, bs[cs]);
    const int gn = base + node;
    g_space[(size_t)gn * SDIM + cs] = v;
    out[(size_t)N * 228 + (size_t)gn * SDIM + cs] = v;   // space output region
}

// ---------------- K1b: prop = x@Wp + bp (register tile 4x4) ----------------
__global__ __launch_bounds__(256) void k1b_prop(
        const float* __restrict__ x,
        const float* __restrict__ Wp, const float* __restrict__ bp) {
    __shared__ __align__(16) float sx [64 * INCH];   // 32 KB
    __shared__ __align__(16) float sWp[INCH * PDIM]; // 32 KB
    const int tid = threadIdx.x;
    const int base = blockIdx.x * 64;

    for (int i = tid * 4; i < 64 * INCH; i += 1024)
        *(float4*)&sx[i] = *(const float4*)&x[(size_t)base * INCH + i];
    for (int i = tid * 4; i < INCH * PDIM; i += 1024)
        *(float4*)&sWp[i] = *(const float4*)&Wp[i];
    __syncthreads();

    const int cg = (tid & 15) * 4;
    const int ng = (tid >> 4) * 4;
    float acc[4][4];
    #pragma unroll
    for (int i = 0; i < 4; i++) {
        const float4 b4 = *(const float4*)&bp[cg];
        acc[i][0] = b4.x; acc[i][1] = b4.y; acc[i][2] = b4.z; acc[i][3] = b4.w;
    }
    for (int kk = 0; kk < INCH; kk += 4) {
        float4 xv[4];
        #pragma unroll
        for (int i = 0; i < 4; i++) xv[i] = *(const float4*)&sx[(ng + i) * INCH + kk];
        #pragma unroll
        for (int q = 0; q < 4; q++) {
            const float4 w4 = *(const float4*)&sWp[(kk + q) * PDIM + cg];
            #pragma unroll
            for (int i = 0; i < 4; i++) {
                const float xs = (q == 0) ? xv[i].x : (q == 1) ? xv[i].y
                               : (q == 2) ? xv[i].z : xv[i].w;
                acc[i][0] = __fmaf_rn(xs, w4.x, acc[i][0]);
                acc[i][1] = __fmaf_rn(xs, w4.y, acc[i][1]);
                acc[i][2] = __fmaf_rn(xs, w4.z, acc[i][2]);
                acc[i][3] = __fmaf_rn(xs, w4.w, acc[i][3]);
            }
        }
    }
    #pragma unroll
    for (int i = 0; i < 4; i++) {
        float4 r; r.x = acc[i][0]; r.y = acc[i][1]; r.z = acc[i][2]; r.w = acc[i][3];
        *(float4*)&g_prop[(size_t)(base + ng + i) * PDIM + cg] = r;
    }
}

// ---------------- K2 v5: R8 skeleton, f32x2 packed sweeps (bit-exact) ----------------
// 256 threads = 8 warps; warp owns 2 queries; 16 queries/block; grid 1024.
// smem: sA uint4[2048] 32KB | sB uint4[2048] 32KB | sSq2 u64[2048] 16KB
//     | sBuf u64[16][CAP=128] 16KB  => 96 KB, 2 CTAs/SM
#define K2_SMEM (NPAIR*16*2 + NPAIR*8 + 16*CAP*8)

__device__ __forceinline__ void k2_write(unsigned vbits, int j, int rank, int gq,
                                         int segBase, float* __restrict__ out, int N) {
    const float v = __uint_as_float(vbits);
    const int gi = segBase + j;
    g_idx[(size_t)gq * KNN + rank] = gi;
    g_w  [(size_t)gq * KNN + rank] = expf(-10.0f * v);
    out[(size_t)N * 128 + (size_t)gq * KNN + rank] = (float)gi;
    out[(size_t)N * 178 + (size_t)gq * KNN + rank] = v;
}

// rank-49 of the 128 clamped subset values (4 per lane), unique synthetic idx
__device__ __forceinline__ float select49_128(u64t* __restrict__ buf,
                                              float e0, float e1, float o0, float o1,
                                              int lane) {
    const unsigned base = lane * 4;
    const u64t k0 = ((u64t)__float_as_uint(e0) << 16) | (base + 0);
    const u64t k1 = ((u64t)__float_as_uint(e1) << 16) | (base + 1);
    const u64t k2 = ((u64t)__float_as_uint(o0) << 16) | (base + 2);
    const u64t k3 = ((u64t)__float_as_uint(o1) << 16) | (base + 3);
    buf[base + 0] = k0; buf[base + 1] = k1; buf[base + 2] = k2; buf[base + 3] = k3;
    __syncwarp();
    int r0 = 0, r1 = 0, r2 = 0, r3 = 0;
    #pragma unroll 8
    for (int n = 0; n < 128; n++) {
        const u64t u = buf[n];
        r0 += (u < k0); r1 += (u < k1); r2 += (u < k2); r3 += (u < k3);
    }
    const bool h = (r0 == 49) || (r1 == 49) || (r2 == 49) || (r3 == 49);
    const float vh = (r0 == 49) ? e0 : ((r1 == 49) ? e1 : ((r2 == 49) ? o0 : o1));
    const unsigned m = __ballot_sync(FULLMASK, h);
    const float res = __shfl_sync(FULLMASK, vh, __ffs(m) - 1);
    __syncwarp();
    return res;
}

__device__ void k2_finalize(const u64t* __restrict__ buf, unsigned cnt, int gq,
                            float4 cq, float sqq, int segBase, int lane,
                            const float4* __restrict__ gs4,
                            float* __restrict__ out, int N) {
    if (cnt >= KNN && cnt <= CAP) {
        for (int m = lane; m < (int)cnt; m += 32) {
            const u64t key = buf[m];
            int rank = 0;
            for (int n = 0; n < (int)cnt; n++) rank += (buf[n] < key);
            if (rank < KNN)
                k2_write((unsigned)(key >> 16), (int)(key & 0xFFFFull), rank, gq, segBase, out, N);
        }
    } else {
        // Exact deterministic fallback (practically never taken).
        long long prev = -1;
        for (int r = 0; r < KNN; r++) {
            u64t best = ~0ull;
            for (int j = lane; j < NPER; j += 32) {
                const float4 cj = gs4[segBase + j];
                const float v = d2f(cq, sqq, cj, xla_sq4(cj));
                const u64t key = ((u64t)__float_as_uint(v) << 16) | (unsigned)j;
                if ((long long)key > prev && key < best) best = key;
            }
            #pragma unroll
            for (int off = 16; off; off >>= 1) {
                const u64t o = __shfl_xor_sync(FULLMASK, best, off);
                if (o < best) best = o;
            }
            if (lane == 0)
                k2_write((unsigned)(best >> 16), (int)(best & 0xFFFFull), r, gq, segBase, out, N);
            prev = (long long)best;
        }
    }
}

__global__ __launch_bounds__(256) void k2_knn(float* __restrict__ out, int N) {
    extern __shared__ unsigned char dsm[];
    uint4* sA   = (uint4*)dsm;                                   // 32 KB (x,y pairs)
    uint4* sB   = (uint4*)(dsm + NPAIR * 16);                    // 32 KB (z,w pairs)
    u64t*  sSq2 = (u64t*)(dsm + NPAIR * 32);                     // 16 KB
    u64t*  sBuf = (u64t*)(dsm + NPAIR * 32 + NPAIR * 8);         // 16 KB
    __shared__ unsigned scnt[16];

    const int tid = threadIdx.x;
    const int w = tid >> 5, lane = tid & 31;
    const int qBase = blockIdx.x * 16;
    const int segBase = qBase & ~(NPER - 1);
    const float4* gs4 = (const float4*)g_space;

    // ---- setup: pair-packed coords + exact packed sq ----
    for (int p = tid; p < NPAIR; p += 256) {
        const float4 c0 = gs4[segBase + 2 * p];
        const float4 c1 = gs4[segBase + 2 * p + 1];
        sA[p] = make_uint4(__float_as_uint(c0.x), __float_as_uint(c1.x),
                           __float_as_uint(c0.y), __float_as_uint(c1.y));
        sB[p] = make_uint4(__float_as_uint(c0.z), __float_as_uint(c1.z),
                           __float_as_uint(c0.w), __float_as_uint(c1.w));
        sSq2[p] = p2_pack(xla_sq4(c0), xla_sq4(c1));
    }
    if (tid < 16) scnt[tid] = 0;
    __syncthreads();

    const int q0 = qBase + 2 * w, q1 = q0 + 1;
    const float4 cq0 = gs4[q0]; const float sqq0 = xla_sq4(cq0);
    const float4 cq1 = gs4[q1]; const float sqq1 = xla_sq4(cq1);
    const u64t q0x = p2_pack(cq0.x, cq0.x), q0y = p2_pack(cq0.y, cq0.y),
               q0z = p2_pack(cq0.z, cq0.z), q0w = p2_pack(cq0.w, cq0.w);
    const u64t q1x = p2_pack(cq1.x, cq1.x), q1y = p2_pack(cq1.y, cq1.y),
               q1z = p2_pack(cq1.z, cq1.z), q1w = p2_pack(cq1.w, cq1.w);
    const u64t sqq0p = p2_pack(sqq0, sqq0), sqq1p = p2_pack(sqq1, sqq1);
    const u64t neg2  = p2_pack(-2.0f, -2.0f);
    u64t* buf0 = sBuf + (size_t)(2 * w) * CAP;
    u64t* buf1 = buf0 + CAP;

    // ---- Pass 1: per-lane per-stream (even/odd) top-2, raw (unclamped) values ----
    float aE0 = INFINITY, aE1 = INFINITY, aO0 = INFINITY, aO1 = INFINITY;  // q0
    float bE0 = INFINITY, bE1 = INFINITY, bO0 = INFINITY, bO1 = INFINITY;  // q1
    for (int p = lane; p < NPAIR; p += 32) {
        const uint4 A = sA[p]; const uint4 B = sB[p]; const u64t sj2 = sSq2[p];
        {
            const u64t r2 = d2pair(q0x, q0y, q0z, q0w, sqq0p, A, B, sj2, neg2);
            float vE, vO; p2_unpack(r2, vE, vO);
            TOP2_UPD(aE0, aE1, vE);
            TOP2_UPD(aO0, aO1, vO);
        }
        {
            const u64t r2 = d2pair(q1x, q1y, q1z, q1w, sqq1p, A, B, sj2, neg2);
            float vE, vO; p2_unpack(r2, vE, vO);
            TOP2_UPD(bE0, bE1, vE);
            TOP2_UPD(bO0, bO1, vO);
        }
    }

    // ---- Thresholds: rank-49 of 128-subset (clamped before bit-keying) ----
    const float T0 = select49_128(buf0, fmaxf(aE0, 0.0f), fmaxf(aE1, 0.0f),
                                         fmaxf(aO0, 0.0f), fmaxf(aO1, 0.0f), lane);
    const float T1 = select49_128(buf1, fmaxf(bE0, 0.0f), fmaxf(bE1, 0.0f),
                                         fmaxf(bO0, 0.0f), fmaxf(bO1, 0.0f), lane);

    // ---- Pass 2: recompute raw pairs, collect clamped hits ----
    unsigned* cnt0 = &scnt[2 * w];
    unsigned* cnt1 = &scnt[2 * w + 1];
    for (int p = lane; p < NPAIR; p += 32) {
        const uint4 A = sA[p]; const uint4 B = sB[p]; const u64t sj2 = sSq2[p];
        {
            const u64t r2 = d2pair(q0x, q0y, q0z, q0w, sqq0p, A, B, sj2, neg2);
            float vE, vO; p2_unpack(r2, vE, vO);
            if (vE <= T0) {
                const unsigned pos = atomicAdd(cnt0, 1u);
                if (pos < CAP)
                    buf0[pos] = ((u64t)__float_as_uint(fmaxf(vE, 0.0f)) << 16) | (unsigned)(2 * p);
            }
            if (vO <= T0) {
                const unsigned pos = atomicAdd(cnt0, 1u);
                if (pos < CAP)
                    buf0[pos] = ((u64t)__float_as_uint(fmaxf(vO, 0.0f)) << 16) | (unsigned)(2 * p + 1);
            }
        }
        {
            const u64t r2 = d2pair(q1x, q1y, q1z, q1w, sqq1p, A, B, sj2, neg2);
            float vE, vO; p2_unpack(r2, vE, vO);
            if (vE <= T1) {
                const unsigned pos = atomicAdd(cnt1, 1u);
                if (pos < CAP)
                    buf1[pos] = ((u64t)__float_as_uint(fmaxf(vE, 0.0f)) << 16) | (unsigned)(2 * p);
            }
            if (vO <= T1) {
                const unsigned pos = atomicAdd(cnt1, 1u);
                if (pos < CAP)
                    buf1[pos] = ((u64t)__float_as_uint(fmaxf(vO, 0.0f)) << 16) | (unsigned)(2 * p + 1);
            }
        }
    }
    __syncwarp();

    // ---- Final exact rank-sort + writes ----
    k2_finalize(buf0, *cnt0, q0, cq0, sqq0, segBase, lane, gs4, out, N);
    k2_finalize(buf1, *cnt1, q1, cq1, sqq1, segBase, lane, gs4, out, N);
}

// ---------------- K3: gather + mean/max + output GEMM + relu ----------------
__global__ __launch_bounds__(256) void k3_aggregate(
        const float* __restrict__ x,
        const float* __restrict__ Wo, const float* __restrict__ bo,
        float* __restrict__ out) {
    __shared__ __align__(16) float feat[32][2 * PDIM + INCH];   // 32 KB
    __shared__ float swarr[32 * KNN];
    __shared__ int   sgidx[32 * KNN];

    const int tid = threadIdx.x;
    const int base = blockIdx.x * 32;

    for (int i = tid * 4; i < 32 * INCH; i += 1024) {
        const int node = i >> 7, c = i & 127;
        *(float4*)&feat[node][c] = *(const float4*)&x[(size_t)(base + node) * INCH + c];
    }
    for (int i = tid; i < 32 * KNN; i += 256) {
        swarr[i] = g_w  [(size_t)base * KNN + i];
        sgidx[i] = g_idx[(size_t)base * KNN + i];
    }
    __syncthreads();

    {
        const int ns = tid >> 6, c = tid & 63;
        for (int nn = ns; nn < 32; nn += 4) {
            const float* wr = &swarr[nn * KNN];
            const int*   ir = &sgidx[nn * KNN];
            float acc = 0.0f, mx = -INFINITY;
            #pragma unroll 5
            for (int r = 0; r < KNN; r++) {
                const float v = g_prop[(size_t)ir[r] * PDIM + c] * wr[r];
                acc += v; mx = fmaxf(mx, v);
            }
            feat[nn][INCH + c]        = acc * (1.0f / (float)KNN);
            feat[nn][INCH + PDIM + c] = mx;
        }
    }
    __syncthreads();

    const int c = tid & 127;
    const int t0 = (tid >> 7) * 16;
    float acc[16];
    #pragma unroll
    for (int t = 0; t < 16; t++) acc[t] = bo[c];
    for (int kk = 0; kk < 2 * PDIM + INCH; kk += 4) {
        const float w0 = Wo[(size_t)(kk + 0) * OUTCH + c];
        const float w1 = Wo[(size_t)(kk + 1) * OUTCH + c];
        const float w2 = Wo[(size_t)(kk + 2) * OUTCH + c];
        const float w3 = Wo[(size_t)(kk + 3) * OUTCH + c];
        #pragma unroll
        for (int t = 0; t < 16; t++) {
            const float4 f = *(const float4*)&feat[t0 + t][kk];
            acc[t] = __fmaf_rn(f.x, w0, acc[t]);
            acc[t] = __fmaf_rn(f.y, w1, acc[t]);
            acc[t] = __fmaf_rn(f.z, w2, acc[t]);
            acc[t] = __fmaf_rn(f.w, w3, acc[t]);
        }
    }
    #pragma unroll
    for (int t = 0; t < 16; t++)
        out[(size_t)(base + t0 + t) * OUTCH + c] = fmaxf(acc[t], 0.0f);
}

// ---------------- launch ----------------
extern "C" void kernel_launch(void* const* d_in, const int* in_sizes, int n_in,
                              void* d_out, int out_size) {
    const float* x  = (const float*)d_in[0];
    const float* Ws = (const float*)d_in[2];
    const float* bs = (const float*)d_in[3];
    const float* Wp = (const float*)d_in[4];
    const float* bp = (const float*)d_in[5];
    const float* Wo = (const float*)d_in[6];
    const float* bo = (const float*)d_in[7];

    const int N = in_sizes[0] / INCH;   // 16384
    float* out = (float*)d_out;

    k1a_space<<<N / 64, 256>>>(x, Ws, bs, out, N);
    k1b_prop <<<N / 64, 256>>>(x, Wp, bp);

    cudaFuncSetAttribute(k2_knn, cudaFuncAttributeMaxDynamicSharedMemorySize, K2_SMEM);
    k2_knn<<<N / 16, 256, K2_SMEM>>>(out, N);

    k3_aggregate<<<N / 32, 256>>>(x, Wo, bo, out);

    (void)n_in; (void)in_sizes; (void)out_size;
}

// round 12
// speedup vs baseline: 1.7003x; 1.0723x over previous
#include <cuda_runtime.h>
#include <cuda_bf16.h>
#include <math.h>

#define FULLMASK 0xFFFFFFFFu

// Problem constants (fixed by the dataset)
#define NMAX   16384
#define INCH   128
#define SDIM   4
#define PDIM   64
#define OUTCH  128
#define KNN    50
#define NPER   4096   // nodes per segment (16384 / 4 splits)
#define NPAIR  (NPER/2)
#define CAP    128    // collection buffer per query

typedef unsigned long long u64t;

// ---------------- device scratch (no allocation allowed) ----------------
__device__ float g_space[NMAX * SDIM];
__device__ float g_prop [NMAX * PDIM];
__device__ int   g_idx  [NMAX * KNN];
__device__ float g_w    [NMAX * KNN];   // exp(-10*d2), precomputed for k3

// Bit-exact replication of reference arithmetic (do not touch):
__device__ __forceinline__ float xla_sq4(float4 c) {
    return __fadd_rn(__fadd_rn(__fadd_rn(__fmul_rn(c.x, c.x), __fmul_rn(c.y, c.y)),
                               __fmul_rn(c.z, c.z)),
                     __fmul_rn(c.w, c.w));
}
__device__ __forceinline__ float cublas_dot4(float4 a, float4 b) {
    return __fmaf_rn(a.w, b.w, __fmaf_rn(a.z, b.z, __fmaf_rn(a.y, b.y, __fmul_rn(a.x, b.x))));
}
__device__ __forceinline__ float d2f(float4 cq, float sqq, float4 cj, float sqj) {
    const float dot = cublas_dot4(cq, cj);
    const float t   = __fadd_rn(sqq, sqj);
    return fmaxf(__fadd_rn(t, __fmul_rn(-2.0f, dot)), 0.0f);
}

// ---------------- packed fp32x2 helpers (sm_103a) ----------------
__device__ __forceinline__ u64t p2_pack(float lo, float hi) {
    u64t r; asm("mov.b64 %0, {%1, %2};" : "=l"(r) : "f"(lo), "f"(hi)); return r;
}
__device__ __forceinline__ void p2_unpack(u64t v, float& lo, float& hi) {
    asm("mov.b64 {%0, %1}, %2;" : "=f"(lo), "=f"(hi) : "l"(v));
}
__device__ __forceinline__ u64t p2_mul(u64t a, u64t b) {
    u64t r; asm("mul.rn.f32x2 %0, %1, %2;" : "=l"(r) : "l"(a), "l"(b)); return r;
}
__device__ __forceinline__ u64t p2_add(u64t a, u64t b) {
    u64t r; asm("add.rn.f32x2 %0, %1, %2;" : "=l"(r) : "l"(a), "l"(b)); return r;
}
__device__ __forceinline__ u64t p2_fma(u64t a, u64t b, u64t c) {
    u64t r; asm("fma.rn.f32x2 %0, %1, %2, %3;" : "=l"(r) : "l"(a), "l"(b), "l"(c)); return r;
}
__device__ __forceinline__ u64t mk64(unsigned lo, unsigned hi) {
    u64t r; asm("mov.b64 %0, {%1, %2};" : "=l"(r) : "r"(lo), "r"(hi)); return r;
}

// per-lane two candidates, one query: same RN op sequence as d2f (per lane)
__device__ __forceinline__ u64t d2pair(u64t qx2, u64t qy2, u64t qz2, u64t qw2,
                                       u64t sqq2, uint4 A, uint4 B, u64t sj2, u64t neg2) {
    const u64t x2 = mk64(A.x, A.y), y2 = mk64(A.z, A.w);
    const u64t z2 = mk64(B.x, B.y), w2 = mk64(B.z, B.w);
    u64t dot = p2_mul(qx2, x2);
    dot = p2_fma(qy2, y2, dot);
    dot = p2_fma(qz2, z2, dot);
    dot = p2_fma(qw2, w2, dot);
    return p2_add(p2_add(sqq2, sj2), p2_mul(neg2, dot));
}

#define TOP2_UPD(a0, a1, v) do { a1 = fminf(a1, fmaxf(a0, v)); a0 = fminf(a0, v); } while (0)

// ---------------- K1: space = x@Ws + bs ; prop = x@Wp + bp ----------------
// 64 nodes/block, 256 threads (measured best: 22.4us).
__global__ __launch_bounds__(256) void k1_project(
        const float* __restrict__ x,
        const float* __restrict__ Ws, const float* __restrict__ bs,
        const float* __restrict__ Wp, const float* __restrict__ bp,
        float* __restrict__ out, int N) {
    __shared__ __align__(16) float sx [64 * INCH];        // 32 KB
    __shared__ __align__(16) float sWp[INCH * PDIM];      // 32 KB
    __shared__ float sWs[INCH * SDIM];                    //  2 KB
    const int tid = threadIdx.x;
    const int base = blockIdx.x * 64;

    for (int i = tid * 4; i < 64 * INCH; i += 1024)
        *(float4*)&sx[i] = *(const float4*)&x[(size_t)base * INCH + i];
    for (int i = tid * 4; i < INCH * PDIM; i += 1024)
        *(float4*)&sWp[i] = *(const float4*)&Wp[i];
    for (int i = tid; i < INCH * SDIM; i += 256) sWs[i] = Ws[i];
    __syncthreads();

    {
        const int cg = (tid & 15) * 4;
        const int ng = (tid >> 4) * 4;
        float acc[4][4];
        #pragma unroll
        for (int i = 0; i < 4; i++) {
            const float4 b4 = *(const float4*)&bp[cg];
            acc[i][0] = b4.x; acc[i][1] = b4.y; acc[i][2] = b4.z; acc[i][3] = b4.w;
        }
        for (int kk = 0; kk < INCH; kk += 4) {
            float4 xv[4];
            #pragma unroll
            for (int i = 0; i < 4; i++) xv[i] = *(const float4*)&sx[(ng + i) * INCH + kk];
            #pragma unroll
            for (int q = 0; q < 4; q++) {
                const float4 w4 = *(const float4*)&sWp[(kk + q) * PDIM + cg];
                #pragma unroll
                for (int i = 0; i < 4; i++) {
                    const float xs = (q == 0) ? xv[i].x : (q == 1) ? xv[i].y
                                   : (q == 2) ? xv[i].z : xv[i].w;
                    acc[i][0] = __fmaf_rn(xs, w4.x, acc[i][0]);
                    acc[i][1] = __fmaf_rn(xs, w4.y, acc[i][1]);
                    acc[i][2] = __fmaf_rn(xs, w4.z, acc[i][2]);
                    acc[i][3] = __fmaf_rn(xs, w4.w, acc[i][3]);
                }
            }
        }
        #pragma unroll
        for (int i = 0; i < 4; i++) {
            float4 r; r.x = acc[i][0]; r.y = acc[i][1]; r.z = acc[i][2]; r.w = acc[i][3];
            *(float4*)&g_prop[(size_t)(base + ng + i) * PDIM + cg] = r;
        }
    }

    {
        const int node = tid >> 2, cs = tid & 3;
        const float* xr = &sx[node * INCH];
        float s[4];
        #pragma unroll
        for (int sl = 0; sl < 4; sl++) {
            float acc = 0.0f;
            const int k0 = sl * 32;
            #pragma unroll
            for (int kk = 0; kk < 32; kk++)
                acc = __fmaf_rn(xr[k0 + kk], sWs[(k0 + kk) * SDIM + cs], acc);
            s[sl] = acc;
        }
        const float g = __fadd_rn(__fadd_rn(__fadd_rn(s[0], s[1]), s[2]), s[3]);
        const float v = __fadd_rn(g, bs[cs]);
        const int gn = base + node;
        g_space[(size_t)gn * SDIM + cs] = v;
        out[(size_t)N * 228 + (size_t)gn * SDIM + cs] = v;
    }
}

// ---------------- K2 v5: R8 skeleton, f32x2 packed sweeps (bit-exact) ----------------
#define K2_SMEM (NPAIR*16*2 + NPAIR*8 + 16*CAP*8)

__device__ __forceinline__ void k2_write(unsigned vbits, int j, int rank, int gq,
                                         int segBase, float* __restrict__ out, int N) {
    const float v = __uint_as_float(vbits);
    const int gi = segBase + j;
    g_idx[(size_t)gq * KNN + rank] = gi;
    g_w  [(size_t)gq * KNN + rank] = expf(-10.0f * v);
    out[(size_t)N * 128 + (size_t)gq * KNN + rank] = (float)gi;
    out[(size_t)N * 178 + (size_t)gq * KNN + rank] = v;
}

__device__ __forceinline__ float select49_128(u64t* __restrict__ buf,
                                              float e0, float e1, float o0, float o1,
                                              int lane) {
    const unsigned base = lane * 4;
    const u64t k0 = ((u64t)__float_as_uint(e0) << 16) | (base + 0);
    const u64t k1 = ((u64t)__float_as_uint(e1) << 16) | (base + 1);
    const u64t k2 = ((u64t)__float_as_uint(o0) << 16) | (base + 2);
    const u64t k3 = ((u64t)__float_as_uint(o1) << 16) | (base + 3);
    buf[base + 0] = k0; buf[base + 1] = k1; buf[base + 2] = k2; buf[base + 3] = k3;
    __syncwarp();
    int r0 = 0, r1 = 0, r2 = 0, r3 = 0;
    #pragma unroll 8
    for (int n = 0; n < 128; n++) {
        const u64t u = buf[n];
        r0 += (u < k0); r1 += (u < k1); r2 += (u < k2); r3 += (u < k3);
    }
    const bool h = (r0 == 49) || (r1 == 49) || (r2 == 49) || (r3 == 49);
    const float vh = (r0 == 49) ? e0 : ((r1 == 49) ? e1 : ((r2 == 49) ? o0 : o1));
    const unsigned m = __ballot_sync(FULLMASK, h);
    const float res = __shfl_sync(FULLMASK, vh, __ffs(m) - 1);
    __syncwarp();
    return res;
}

__device__ void k2_finalize(const u64t* __restrict__ buf, unsigned cnt, int gq,
                            float4 cq, float sqq, int segBase, int lane,
                            const float4* __restrict__ gs4,
                            float* __restrict__ out, int N) {
    if (cnt >= KNN && cnt <= CAP) {
        for (int m = lane; m < (int)cnt; m += 32) {
            const u64t key = buf[m];
            int rank = 0;
            for (int n = 0; n < (int)cnt; n++) rank += (buf[n] < key);
            if (rank < KNN)
                k2_write((unsigned)(key >> 16), (int)(key & 0xFFFFull), rank, gq, segBase, out, N);
        }
    } else {
        long long prev = -1;
        for (int r = 0; r < KNN; r++) {
            u64t best = ~0ull;
            for (int j = lane; j < NPER; j += 32) {
                const float4 cj = gs4[segBase + j];
                const float v = d2f(cq, sqq, cj, xla_sq4(cj));
                const u64t key = ((u64t)__float_as_uint(v) << 16) | (unsigned)j;
                if ((long long)key > prev && key < best) best = key;
            }
            #pragma unroll
            for (int off = 16; off; off >>= 1) {
                const u64t o = __shfl_xor_sync(FULLMASK, best, off);
                if (o < best) best = o;
            }
            if (lane == 0)
                k2_write((unsigned)(best >> 16), (int)(best & 0xFFFFull), r, gq, segBase, out, N);
            prev = (long long)best;
        }
    }
}

__global__ __launch_bounds__(256) void k2_knn(float* __restrict__ out, int N) {
    extern __shared__ unsigned char dsm[];
    uint4* sA   = (uint4*)dsm;                                   // 32 KB (x,y pairs)
    uint4* sB   = (uint4*)(dsm + NPAIR * 16);                    // 32 KB (z,w pairs)
    u64t*  sSq2 = (u64t*)(dsm + NPAIR * 32);                     // 16 KB
    u64t*  sBuf = (u64t*)(dsm + NPAIR * 32 + NPAIR * 8);         // 16 KB
    __shared__ unsigned scnt[16];

    const int tid = threadIdx.x;
    const int w = tid >> 5, lane = tid & 31;
    const int qBase = blockIdx.x * 16;
    const int segBase = qBase & ~(NPER - 1);
    const float4* gs4 = (const float4*)g_space;

    for (int p = tid; p < NPAIR; p += 256) {
        const float4 c0 = gs4[segBase + 2 * p];
        const float4 c1 = gs4[segBase + 2 * p + 1];
        sA[p] = make_uint4(__float_as_uint(c0.x), __float_as_uint(c1.x),
                           __float_as_uint(c0.y), __float_as_uint(c1.y));
        sB[p] = make_uint4(__float_as_uint(c0.z), __float_as_uint(c1.z),
                           __float_as_uint(c0.w), __float_as_uint(c1.w));
        sSq2[p] = p2_pack(xla_sq4(c0), xla_sq4(c1));
    }
    if (tid < 16) scnt[tid] = 0;
    __syncthreads();

    const int q0 = qBase + 2 * w, q1 = q0 + 1;
    const float4 cq0 = gs4[q0]; const float sqq0 = xla_sq4(cq0);
    const float4 cq1 = gs4[q1]; const float sqq1 = xla_sq4(cq1);
    const u64t q0x = p2_pack(cq0.x, cq0.x), q0y = p2_pack(cq0.y, cq0.y),
               q0z = p2_pack(cq0.z, cq0.z), q0w = p2_pack(cq0.w, cq0.w);
    const u64t q1x = p2_pack(cq1.x, cq1.x), q1y = p2_pack(cq1.y, cq1.y),
               q1z = p2_pack(cq1.z, cq1.z), q1w = p2_pack(cq1.w, cq1.w);
    const u64t sqq0p = p2_pack(sqq0, sqq0), sqq1p = p2_pack(sqq1, sqq1);
    const u64t neg2  = p2_pack(-2.0f, -2.0f);
    u64t* buf0 = sBuf + (size_t)(2 * w) * CAP;
    u64t* buf1 = buf0 + CAP;

    float aE0 = INFINITY, aE1 = INFINITY, aO0 = INFINITY, aO1 = INFINITY;
    float bE0 = INFINITY, bE1 = INFINITY, bO0 = INFINITY, bO1 = INFINITY;
    for (int p = lane; p < NPAIR; p += 32) {
        const uint4 A = sA[p]; const uint4 B = sB[p]; const u64t sj2 = sSq2[p];
        {
            const u64t r2 = d2pair(q0x, q0y, q0z, q0w, sqq0p, A, B, sj2, neg2);
            float vE, vO; p2_unpack(r2, vE, vO);
            TOP2_UPD(aE0, aE1, vE);
            TOP2_UPD(aO0, aO1, vO);
        }
        {
            const u64t r2 = d2pair(q1x, q1y, q1z, q1w, sqq1p, A, B, sj2, neg2);
            float vE, vO; p2_unpack(r2, vE, vO);
            TOP2_UPD(bE0, bE1, vE);
            TOP2_UPD(bO0, bO1, vO);
        }
    }

    const float T0 = select49_128(buf0, fmaxf(aE0, 0.0f), fmaxf(aE1, 0.0f),
                                         fmaxf(aO0, 0.0f), fmaxf(aO1, 0.0f), lane);
    const float T1 = select49_128(buf1, fmaxf(bE0, 0.0f), fmaxf(bE1, 0.0f),
                                         fmaxf(bO0, 0.0f), fmaxf(bO1, 0.0f), lane);

    unsigned* cnt0 = &scnt[2 * w];
    unsigned* cnt1 = &scnt[2 * w + 1];
    for (int p = lane; p < NPAIR; p += 32) {
        const uint4 A = sA[p]; const uint4 B = sB[p]; const u64t sj2 = sSq2[p];
        {
            const u64t r2 = d2pair(q0x, q0y, q0z, q0w, sqq0p, A, B, sj2, neg2);
            float vE, vO; p2_unpack(r2, vE, vO);
            if (vE <= T0) {
                const unsigned pos = atomicAdd(cnt0, 1u);
                if (pos < CAP)
                    buf0[pos] = ((u64t)__float_as_uint(fmaxf(vE, 0.0f)) << 16) | (unsigned)(2 * p);
            }
            if (vO <= T0) {
                const unsigned pos = atomicAdd(cnt0, 1u);
                if (pos < CAP)
                    buf0[pos] = ((u64t)__float_as_uint(fmaxf(vO, 0.0f)) << 16) | (unsigned)(2 * p + 1);
            }
        }
        {
            const u64t r2 = d2pair(q1x, q1y, q1z, q1w, sqq1p, A, B, sj2, neg2);
            float vE, vO; p2_unpack(r2, vE, vO);
            if (vE <= T1) {
                const unsigned pos = atomicAdd(cnt1, 1u);
                if (pos < CAP)
                    buf1[pos] = ((u64t)__float_as_uint(fmaxf(vE, 0.0f)) << 16) | (unsigned)(2 * p);
            }
            if (vO <= T1) {
                const unsigned pos = atomicAdd(cnt1, 1u);
                if (pos < CAP)
                    buf1[pos] = ((u64t)__float_as_uint(fmaxf(vO, 0.0f)) << 16) | (unsigned)(2 * p + 1);
            }
        }
    }
    __syncwarp();

    k2_finalize(buf0, *cnt0, q0, cq0, sqq0, segBase, lane, gs4, out, N);
    k2_finalize(buf1, *cnt1, q1, cq1, sqq1, segBase, lane, gs4, out, N);
}

// ---------------- K3 v2: float4 gather + mean/max + output GEMM + relu ----------------
// 32 nodes/block, 256 threads. Gather: 16 threads/node, float4 per thread.
__global__ __launch_bounds__(256) void k3_aggregate(
        const float* __restrict__ x,
        const float* __restrict__ Wo, const float* __restrict__ bo,
        float* __restrict__ out) {
    __shared__ __align__(16) float feat[32][2 * PDIM + INCH];   // 32 KB
    __shared__ float swarr[32 * KNN];                            // 6.4 KB
    __shared__ int   sgidx[32 * KNN];                            // 6.4 KB

    const int tid = threadIdx.x;
    const int base = blockIdx.x * 32;

    for (int i = tid * 4; i < 32 * INCH; i += 1024) {
        const int node = i >> 7, c = i & 127;
        *(float4*)&feat[node][c] = *(const float4*)&x[(size_t)(base + node) * INCH + c];
    }
    for (int i = tid; i < 32 * KNN; i += 256) {
        swarr[i] = g_w  [(size_t)base * KNN + i];
        sgidx[i] = g_idx[(size_t)base * KNN + i];
    }
    __syncthreads();

    // Gather: node = tid>>4 (+16 on 2nd pass), channels c4..c4+3 per thread.
    {
        const int nn0 = tid >> 4;          // 0..15
        const int c4  = (tid & 15) * 4;    // 0,4,...,60
        #pragma unroll
        for (int pass = 0; pass < 2; pass++) {
            const int nn = nn0 + pass * 16;
            const int*   ir = &sgidx[nn * KNN];
            const float* wr = &swarr[nn * KNN];
            float ax = 0.0f, ay = 0.0f, az = 0.0f, aw = 0.0f;
            float mx = -INFINITY, my = -INFINITY, mz = -INFINITY, mw = -INFINITY;
            #pragma unroll 5
            for (int r = 0; r < KNN; r++) {
                const float4 p = *(const float4*)&g_prop[(size_t)ir[r] * PDIM + c4];
                const float wv = wr[r];
                const float vx = p.x * wv, vy = p.y * wv, vz = p.z * wv, vw = p.w * wv;
                ax += vx; ay += vy; az += vz; aw += vw;
                mx = fmaxf(mx, vx); my = fmaxf(my, vy);
                mz = fmaxf(mz, vz); mw = fmaxf(mw, vw);
            }
            const float s = 1.0f / (float)KNN;
            float4 fm; fm.x = ax * s; fm.y = ay * s; fm.z = az * s; fm.w = aw * s;
            float4 fx; fx.x = mx; fx.y = my; fx.z = mz; fx.w = mw;
            *(float4*)&feat[nn][INCH + c4]        = fm;
            *(float4*)&feat[nn][INCH + PDIM + c4] = fx;
        }
    }
    __syncthreads();

    // GEMM: c = tid%128; half = tid/128 handles 16 nodes.
    const int c = tid & 127;
    const int t0 = (tid >> 7) * 16;
    float acc[16];
    #pragma unroll
    for (int t = 0; t < 16; t++) acc[t] = bo[c];
    for (int kk = 0; kk < 2 * PDIM + INCH; kk += 4) {
        const float w0 = Wo[(size_t)(kk + 0) * OUTCH + c];
        const float w1 = Wo[(size_t)(kk + 1) * OUTCH + c];
        const float w2 = Wo[(size_t)(kk + 2) * OUTCH + c];
        const float w3 = Wo[(size_t)(kk + 3) * OUTCH + c];
        #pragma unroll
        for (int t = 0; t < 16; t++) {
            const float4 f = *(const float4*)&feat[t0 + t][kk];
            acc[t] = __fmaf_rn(f.x, w0, acc[t]);
            acc[t] = __fmaf_rn(f.y, w1, acc[t]);
            acc[t] = __fmaf_rn(f.z, w2, acc[t]);
            acc[t] = __fmaf_rn(f.w, w3, acc[t]);
        }
    }
    #pragma unroll
    for (int t = 0; t < 16; t++)
        out[(size_t)(base + t0 + t) * OUTCH + c] = fmaxf(acc[t], 0.0f);
}

// ---------------- launch ----------------
extern "C" void kernel_launch(void* const* d_in, const int* in_sizes, int n_in,
                              void* d_out, int out_size) {
    const float* x  = (const float*)d_in[0];
    const float* Ws = (const float*)d_in[2];
    const float* bs = (const float*)d_in[3];
    const float* Wp = (const float*)d_in[4];
    const float* bp = (const float*)d_in[5];
    const float* Wo = (const float*)d_in[6];
    const float* bo = (const float*)d_in[7];

    const int N = in_sizes[0] / INCH;   // 16384
    float* out = (float*)d_out;

    k1_project<<<N / 64, 256>>>(x, Ws, bs, Wp, bp, out, N);

    cudaFuncSetAttribute(k2_knn, cudaFuncAttributeMaxDynamicSharedMemorySize, K2_SMEM);
    k2_knn<<<N / 16, 256, K2_SMEM>>>(out, N);

    k3_aggregate<<<N / 32, 256>>>(x, Wo, bo, out);

    (void)n_in; (void)in_sizes; (void)out_size;
}